// round 6
// baseline (speedup 1.0000x reference)
#include <cuda_runtime.h>
#include <cuda_fp16.h>
#include <cstdint>
#include <math.h>

#define B_DIM 16
#define C_DIM 512
#define S_DIM 1024
#define NG    32
#define NH    8
#define HD    64

// ---------------- scratch (allocation-free __device__ globals) ----------------
__device__ __half g_h   [(size_t)B_DIM * S_DIM * C_DIM];          // [b,s,c]  16 MB
__device__ __half g_qkv [(size_t)B_DIM * S_DIM * 3 * C_DIM];      // [b,s,o]  48 MB
__device__ __half g_o   [(size_t)B_DIM * S_DIM * C_DIM];          // [b,s,c]  16 MB
__device__ __half g_wq  [3 * C_DIM * C_DIM];
__device__ __half g_wp  [C_DIM * C_DIM];
__device__ float  g_mean[B_DIM * NG];
__device__ float  g_inv [B_DIM * NG];

// ---------------- helpers ----------------
__device__ __forceinline__ uint32_t smem_u32(const void* p) {
    return (uint32_t)__cvta_generic_to_shared(p);
}
__device__ __forceinline__ void cp16(void* smem_dst, const void* gmem_src) {
    asm volatile("cp.async.ca.shared.global [%0], [%1], 16;"
                 :: "r"(smem_u32(smem_dst)), "l"(gmem_src));
}
__device__ __forceinline__ void cp_commit() {
    asm volatile("cp.async.commit_group;" ::: "memory");
}
template <int N>
__device__ __forceinline__ void cp_wait() {
    asm volatile("cp.async.wait_group %0;" :: "n"(N) : "memory");
}
__device__ __forceinline__ void ldm_x4(uint32_t& r0, uint32_t& r1, uint32_t& r2,
                                       uint32_t& r3, const void* p) {
    asm volatile("ldmatrix.sync.aligned.m8n8.x4.shared.b16 {%0,%1,%2,%3}, [%4];"
                 : "=r"(r0), "=r"(r1), "=r"(r2), "=r"(r3) : "r"(smem_u32(p)));
}
__device__ __forceinline__ void ldm_x4t(uint32_t& r0, uint32_t& r1, uint32_t& r2,
                                        uint32_t& r3, const void* p) {
    asm volatile("ldmatrix.sync.aligned.m8n8.x4.trans.shared.b16 {%0,%1,%2,%3}, [%4];"
                 : "=r"(r0), "=r"(r1), "=r"(r2), "=r"(r3) : "r"(smem_u32(p)));
}
__device__ __forceinline__ void mma16816(float* c, const uint32_t* a, const uint32_t* b) {
    asm volatile(
        "mma.sync.aligned.m16n8k16.row.col.f32.f16.f16.f32 "
        "{%0,%1,%2,%3}, {%4,%5,%6,%7}, {%8,%9}, {%0,%1,%2,%3};"
        : "+f"(c[0]), "+f"(c[1]), "+f"(c[2]), "+f"(c[3])
        : "r"(a[0]), "r"(a[1]), "r"(a[2]), "r"(a[3]), "r"(b[0]), "r"(b[1]));
}
__device__ __forceinline__ float ex2(float x) {
    float y;
    asm("ex2.approx.ftz.f32 %0, %1;" : "=f"(y) : "f"(x));
    return y;
}
__device__ __forceinline__ uint32_t ex2_h2(uint32_t x) {
    uint32_t y;
    asm("ex2.approx.f16x2 %0, %1;" : "=r"(y) : "r"(x));
    return y;
}
__device__ __forceinline__ uint32_t h2_as_u32(__half2 h) {
    return *reinterpret_cast<uint32_t*>(&h);
}
__device__ __forceinline__ __half2 u32_as_h2(uint32_t u) {
    return *reinterpret_cast<__half2*>(&u);
}

// ---------------------------------------------------------------------------
// fp32 -> fp16 weight convert
// ---------------------------------------------------------------------------
__global__ void convert_kernel(const float* __restrict__ src,
                               __half* __restrict__ dst, int n) {
    int i = blockIdx.x * blockDim.x + threadIdx.x;
    if (i < n) dst[i] = __float2half(src[i]);
}

// ---------------------------------------------------------------------------
// GroupNorm pass 1: per (b,g) mean / inv-std
// ---------------------------------------------------------------------------
__global__ void gn_stats_kernel(const float* __restrict__ x,
                                float* __restrict__ meanArr,
                                float* __restrict__ invArr) {
    const int bg = blockIdx.x;
    const int NEL = (C_DIM / NG) * S_DIM;
    const float* xp = x + (size_t)bg * NEL;
    float sum = 0.f, sq = 0.f;
    for (int i = threadIdx.x; i < NEL; i += 256) {
        float v = xp[i];
        sum += v; sq += v * v;
    }
    __shared__ float ssum[256], ssq[256];
    ssum[threadIdx.x] = sum; ssq[threadIdx.x] = sq;
    __syncthreads();
    for (int s = 128; s > 0; s >>= 1) {
        if (threadIdx.x < s) {
            ssum[threadIdx.x] += ssum[threadIdx.x + s];
            ssq[threadIdx.x]  += ssq[threadIdx.x + s];
        }
        __syncthreads();
    }
    if (threadIdx.x == 0) {
        float mean = ssum[0] * (1.f / NEL);
        float var  = ssq[0] * (1.f / NEL) - mean * mean;
        meanArr[bg] = mean;
        invArr[bg]  = rsqrtf(var + 1e-5f);
    }
}

// ---------------------------------------------------------------------------
// GroupNorm pass 2 + transpose -> h[b,s,c] fp16
// ---------------------------------------------------------------------------
__global__ void gn_transpose_kernel(const float* __restrict__ x,
                                    const float* __restrict__ gamma,
                                    const float* __restrict__ beta,
                                    const float* __restrict__ meanArr,
                                    const float* __restrict__ invArr,
                                    __half* __restrict__ h) {
    __shared__ float t[32][33];
    const int b = blockIdx.z, c0 = blockIdx.y * 32, s0 = blockIdx.x * 32;
    const int tx = threadIdx.x, ty = threadIdx.y;
#pragma unroll
    for (int i = 0; i < 4; i++) {
        int c = c0 + ty + i * 8;
        float v = x[((size_t)b * C_DIM + c) * S_DIM + s0 + tx];
        int g = c >> 4;
        float mean = meanArr[b * NG + g], inv = invArr[b * NG + g];
        t[ty + i * 8][tx] = (v - mean) * inv * gamma[c] + beta[c];
    }
    __syncthreads();
#pragma unroll
    for (int i = 0; i < 4; i++) {
        int s = s0 + ty + i * 8;
        h[((size_t)b * S_DIM + s) * C_DIM + c0 + tx] = __float2half(t[tx][ty + i * 8]);
    }
}

// ---------------------------------------------------------------------------
// Fused flash attention (fp16 mma, fp32 online softmax, f16x2 exp).
// Grid: (S/128, B*NH). 256 thr = 8 warps; warp w owns rows s0+w*16..+15.
// ---------------------------------------------------------------------------
#define SMK 72
#define FLASH_SMEM (5 * 128 * SMK * 2)

__global__ __launch_bounds__(256)
void flash_kernel(const __half* __restrict__ qkv, __half* __restrict__ o) {
    extern __shared__ __half sm[];
    __half (*Qs)[SMK] = reinterpret_cast<__half(*)[SMK]>(sm);
    __half (*Ks)[SMK] = reinterpret_cast<__half(*)[SMK]>(sm + 128 * SMK);
    __half (*Vs)[SMK] = reinterpret_cast<__half(*)[SMK]>(sm + 3 * 128 * SMK);

    const int tid = threadIdx.x, lane = tid & 31, w = tid >> 5;
    const int bh = blockIdx.y, b = bh >> 3, hh = bh & 7;
    const int s0 = blockIdx.x * 128;

    const __half* qbase = qkv + (size_t)b * (S_DIM * 3 * C_DIM) + hh * 64;
    const __half* kbase = qbase + 512;
    const __half* vbase = qbase + 1024;

    const int ldrow = tid >> 1;
    const int ldcol = (tid & 1) * 32;

#pragma unroll
    for (int c = 0; c < 4; c++)
        cp16(&Qs[ldrow][ldcol + c * 8],
             qbase + (size_t)(s0 + ldrow) * 1536 + ldcol + c * 8);
    cp_commit();
    {
        const __half* kp = kbase + (size_t)ldrow * 1536 + ldcol;
        const __half* vp = vbase + (size_t)ldrow * 1536 + ldcol;
#pragma unroll
        for (int c = 0; c < 4; c++) {
            cp16(&Ks[ldrow][ldcol + c * 8], kp + c * 8);
            cp16(&Vs[ldrow][ldcol + c * 8], vp + c * 8);
        }
    }
    cp_commit();
    cp_wait<1>();
    __syncthreads();

    uint32_t qf[4][4];
#pragma unroll
    for (int kj = 0; kj < 4; kj++)
        ldm_x4(qf[kj][0], qf[kj][1], qf[kj][2], qf[kj][3],
               &Qs[w * 16 + (lane & 15)][kj * 16 + ((lane >> 4) << 3)]);

    const float C2 = 0.125f * 1.44269504f;
    float m0 = -1e30f, m1 = -1e30f, l0 = 0.f, l1 = 0.f;
    float ao[8][4];
#pragma unroll
    for (int i = 0; i < 8; i++)
#pragma unroll
        for (int j = 0; j < 4; j++) ao[i][j] = 0.f;

    for (int it = 0; it < 8; it++) {
        if (it < 7) {
            const int stn = (it + 1) & 1;
            const __half* kp = kbase + (size_t)((it + 1) * 128 + ldrow) * 1536 + ldcol;
            const __half* vp = vbase + (size_t)((it + 1) * 128 + ldrow) * 1536 + ldcol;
#pragma unroll
            for (int c = 0; c < 4; c++) {
                cp16(&Ks[stn * 128 + ldrow][ldcol + c * 8], kp + c * 8);
                cp16(&Vs[stn * 128 + ldrow][ldcol + c * 8], vp + c * 8);
            }
            cp_commit();
            cp_wait<1>();
        } else {
            cp_wait<0>();
        }
        __syncthreads();
        const int st = it & 1;

        // ---- S = Q K^T ----
        float as[16][4];
#pragma unroll
        for (int i = 0; i < 16; i++)
#pragma unroll
            for (int j = 0; j < 4; j++) as[i][j] = 0.f;

#pragma unroll
        for (int kj = 0; kj < 4; kj++) {
            uint32_t bf[8][4];
#pragma unroll
            for (int j = 0; j < 8; j++)
                ldm_x4(bf[j][0], bf[j][1], bf[j][2], bf[j][3],
                       &Ks[st * 128 + j * 16 + (lane & 15)]
                          [kj * 16 + ((lane >> 4) << 3)]);
#pragma unroll
            for (int j = 0; j < 8; j++) {
                uint32_t bA[2] = {bf[j][0], bf[j][2]};
                uint32_t bB[2] = {bf[j][1], bf[j][3]};
                mma16816(as[2 * j],     qf[kj], bA);
                mma16816(as[2 * j + 1], qf[kj], bB);
            }
        }

        // ---- online softmax (f16x2 exp) ----
        float mx0 = -1e30f, mx1 = -1e30f;
#pragma unroll
        for (int nt = 0; nt < 16; nt++) {
            mx0 = fmaxf(mx0, fmaxf(as[nt][0], as[nt][1]));
            mx1 = fmaxf(mx1, fmaxf(as[nt][2], as[nt][3]));
        }
        mx0 = fmaxf(mx0, __shfl_xor_sync(0xffffffffu, mx0, 1));
        mx0 = fmaxf(mx0, __shfl_xor_sync(0xffffffffu, mx0, 2));
        mx1 = fmaxf(mx1, __shfl_xor_sync(0xffffffffu, mx1, 1));
        mx1 = fmaxf(mx1, __shfl_xor_sync(0xffffffffu, mx1, 2));
        const float mn0 = fmaxf(m0, mx0), mn1 = fmaxf(m1, mx1);
        const float cr0 = ex2((m0 - mn0) * C2), cr1 = ex2((m1 - mn1) * C2);
        m0 = mn0; m1 = mn1;
        l0 *= cr0; l1 *= cr1;
#pragma unroll
        for (int tn = 0; tn < 8; tn++) {
            ao[tn][0] *= cr0; ao[tn][1] *= cr0;
            ao[tn][2] *= cr1; ao[tn][3] *= cr1;
        }

        uint32_t ph[8][4];
        float sum0 = 0.f, sum1 = 0.f;
#pragma unroll
        for (int nt = 0; nt < 16; nt++) {
            uint32_t e01 = h2_as_u32(__floats2half2_rn((as[nt][0] - mn0) * C2,
                                                       (as[nt][1] - mn0) * C2));
            uint32_t e23 = h2_as_u32(__floats2half2_rn((as[nt][2] - mn1) * C2,
                                                       (as[nt][3] - mn1) * C2));
            uint32_t p01 = ex2_h2(e01);
            uint32_t p23 = ex2_h2(e23);
            float2 f01 = __half22float2(u32_as_h2(p01));
            float2 f23 = __half22float2(u32_as_h2(p23));
            sum0 += f01.x + f01.y;
            sum1 += f23.x + f23.y;
            const int kj = nt >> 1, hi = (nt & 1) * 2;
            ph[kj][hi]     = p01;
            ph[kj][hi + 1] = p23;
        }
        sum0 += __shfl_xor_sync(0xffffffffu, sum0, 1);
        sum0 += __shfl_xor_sync(0xffffffffu, sum0, 2);
        sum1 += __shfl_xor_sync(0xffffffffu, sum1, 1);
        sum1 += __shfl_xor_sync(0xffffffffu, sum1, 2);
        l0 += sum0; l1 += sum1;

        // ---- O += P V ----
#pragma unroll
        for (int kj = 0; kj < 8; kj++) {
            uint32_t vf[4][4];
#pragma unroll
            for (int dj = 0; dj < 4; dj++)
                ldm_x4t(vf[dj][0], vf[dj][1], vf[dj][2], vf[dj][3],
                        &Vs[st * 128 + kj * 16 + (lane & 15)]
                           [dj * 16 + ((lane >> 4) << 3)]);
#pragma unroll
            for (int dj = 0; dj < 4; dj++) {
                uint32_t bA[2] = {vf[dj][0], vf[dj][1]};
                uint32_t bB[2] = {vf[dj][2], vf[dj][3]};
                mma16816(ao[2 * dj],     ph[kj], bA);
                mma16816(ao[2 * dj + 1], ph[kj], bB);
            }
        }
        __syncthreads();
    }

    const float r0 = 1.f / l0, r1 = 1.f / l1;
    const int g = lane >> 2;
    const int srow = s0 + w * 16 + g;
    __half* op = o + ((size_t)b * S_DIM + srow) * C_DIM + hh * 64 + (lane & 3) * 2;
#pragma unroll
    for (int tn = 0; tn < 8; tn++) {
        *(__half2*)(op + tn * 8) =
            __floats2half2_rn(ao[tn][0] * r0, ao[tn][1] * r0);
        *(__half2*)(op + 8 * C_DIM + tn * 8) =
            __floats2half2_rn(ao[tn][2] * r1, ao[tn][3] * r1);
    }
}

// ---------------------------------------------------------------------------
// HGEMM: BM=128, BN=256, BK=32, 256 thr, 8 warps (2m x 4n), warp tile 64x64.
//   D[m,n] = alpha * sum_k A[m,k]*B[n,k] (+bias) (+resid), stored C[m*ldc+n]
//   BIAS_MODE: 0 none, 1 per-m, 2 per-n.
// ---------------------------------------------------------------------------
#define HG_BM 128
#define HG_BN 256
#define HG_SK 40
#define HG_SMEM (2 * (HG_BM + HG_BN) * HG_SK * 2)

template <int BIAS_MODE, bool RESID, typename OutT>
__global__ __launch_bounds__(256, 1)
void hgemm_kernel(const __half* __restrict__ A, const __half* __restrict__ B,
                  OutT* __restrict__ C, const float* __restrict__ bias,
                  const float* __restrict__ resid,
                  int K, int lda, int ldb, int ldc, int nInner,
                  long sAo, long sAi, long sBo, long sBi,
                  long sCo, long sCi, float alpha) {
    extern __shared__ __half hsm[];
    __half (*As)[HG_BM][HG_SK] = reinterpret_cast<__half(*)[HG_BM][HG_SK]>(hsm);
    __half (*Bs)[HG_BN][HG_SK] =
        reinterpret_cast<__half(*)[HG_BN][HG_SK]>(hsm + 2 * HG_BM * HG_SK);

    const int tid = threadIdx.x;
    const int lane = tid & 31, wid = tid >> 5;
    const int wm = wid & 1, wn = wid >> 1;

    const int z = blockIdx.z;
    const int zo = z / nInner, zi = z - zo * nInner;
    A += zo * sAo + zi * sAi;
    B += zo * sBo + zi * sBi;
    const size_t cbase = (size_t)(zo * sCo + zi * sCi);
    const int m0 = blockIdx.y * HG_BM;
    const int n0 = blockIdx.x * HG_BN;

    const int lrow = tid >> 2;            // 0..63
    const int lcol = (tid & 3) * 8;

    float acc[4][8][4];
#pragma unroll
    for (int i = 0; i < 4; i++)
#pragma unroll
        for (int j = 0; j < 8; j++)
#pragma unroll
            for (int q = 0; q < 4; q++) acc[i][j][q] = 0.f;

    const int nit = K >> 5;

    auto load_stage = [&](int st, int it) {
        const int k0 = it << 5;
#pragma unroll
        for (int p = 0; p < 2; p++) {
            int r = lrow + p * 64;
            cp16(&As[st][r][lcol], A + (size_t)(m0 + r) * lda + k0 + lcol);
        }
#pragma unroll
        for (int p = 0; p < 4; p++) {
            int r = lrow + p * 64;
            cp16(&Bs[st][r][lcol], B + (size_t)(n0 + r) * ldb + k0 + lcol);
        }
        cp_commit();
    };

    load_stage(0, 0);

    for (int it = 0; it < nit; it++) {
        if (it + 1 < nit) {
            load_stage((it + 1) & 1, it + 1);
            cp_wait<1>();
        } else {
            cp_wait<0>();
        }
        __syncthreads();

        const int st = it & 1;
#pragma unroll
        for (int ks = 0; ks < 2; ks++) {
            const int kb = ks * 16;
            uint32_t a[4][4], bf[4][4];
#pragma unroll
            for (int tm = 0; tm < 4; tm++)
                ldm_x4(a[tm][0], a[tm][1], a[tm][2], a[tm][3],
                       &As[st][wm * 64 + tm * 16 + (lane & 15)][kb + ((lane >> 4) << 3)]);
#pragma unroll
            for (int bt = 0; bt < 4; bt++)
                ldm_x4(bf[bt][0], bf[bt][1], bf[bt][2], bf[bt][3],
                       &Bs[st][wn * 64 + bt * 16 + (lane & 15)][kb + ((lane >> 4) << 3)]);
#pragma unroll
            for (int tm = 0; tm < 4; tm++)
#pragma unroll
                for (int bt = 0; bt < 4; bt++) {
                    uint32_t bA[2] = {bf[bt][0], bf[bt][2]};
                    uint32_t bB[2] = {bf[bt][1], bf[bt][3]};
                    mma16816(acc[tm][2 * bt],     a[tm], bA);
                    mma16816(acc[tm][2 * bt + 1], a[tm], bB);
                }
        }
        __syncthreads();
    }

#pragma unroll
    for (int tm = 0; tm < 4; tm++) {
        const int row = m0 + wm * 64 + tm * 16 + (lane >> 2);
#pragma unroll
        for (int tn = 0; tn < 8; tn++) {
            const int col = n0 + wn * 64 + tn * 8 + (lane & 3) * 2;
            float v0 = acc[tm][tn][0] * alpha, v1 = acc[tm][tn][1] * alpha;
            float v2 = acc[tm][tn][2] * alpha, v3 = acc[tm][tn][3] * alpha;
            if (BIAS_MODE == 1) {
                v0 += bias[row]; v1 += bias[row];
                v2 += bias[row + 8]; v3 += bias[row + 8];
            }
            if (BIAS_MODE == 2) {
                v0 += bias[col]; v2 += bias[col];
                v1 += bias[col + 1]; v3 += bias[col + 1];
            }
            const size_t a0 = cbase + (size_t)row * ldc + col;
            const size_t a1 = cbase + (size_t)(row + 8) * ldc + col;
            if (sizeof(OutT) == 4) {
                float2 q0 = make_float2(v0, v1), q1 = make_float2(v2, v3);
                if (RESID) {
                    float2 x0 = *(const float2*)(resid + a0);
                    float2 x1 = *(const float2*)(resid + a1);
                    q0.x += x0.x; q0.y += x0.y; q1.x += x1.x; q1.y += x1.y;
                }
                *(float2*)((float*)C + a0) = q0;
                *(float2*)((float*)C + a1) = q1;
            } else {
                *(__half2*)((__half*)C + a0) = __floats2half2_rn(v0, v1);
                *(__half2*)((__half*)C + a1) = __floats2half2_rn(v2, v3);
            }
        }
    }
}

// ---------------------------------------------------------------------------
// Launch
// ---------------------------------------------------------------------------
extern "C" void kernel_launch(void* const* d_in, const int* in_sizes, int n_in,
                              void* d_out, int out_size) {
    const float* x      = (const float*)d_in[0];
    const float* norm_w = (const float*)d_in[1];
    const float* norm_b = (const float*)d_in[2];
    const float* qkv_w  = (const float*)d_in[3];
    const float* qkv_b  = (const float*)d_in[4];
    const float* proj_w = (const float*)d_in[5];
    const float* proj_b = (const float*)d_in[6];
    float* out = (float*)d_out;

    __half *h, *qkv, *obuf, *wq, *wp;
    float *meanA, *invA;
    cudaGetSymbolAddress((void**)&h,     g_h);
    cudaGetSymbolAddress((void**)&qkv,   g_qkv);
    cudaGetSymbolAddress((void**)&obuf,  g_o);
    cudaGetSymbolAddress((void**)&wq,    g_wq);
    cudaGetSymbolAddress((void**)&wp,    g_wp);
    cudaGetSymbolAddress((void**)&meanA, g_mean);
    cudaGetSymbolAddress((void**)&invA,  g_inv);

    const long SC  = (long)S_DIM * C_DIM;
    const long S3C = (long)S_DIM * 3 * C_DIM;

    // 0. fp16 weight copies
    convert_kernel<<<(3 * C_DIM * C_DIM + 255) / 256, 256>>>(qkv_w, wq, 3 * C_DIM * C_DIM);
    convert_kernel<<<(C_DIM * C_DIM + 255) / 256, 256>>>(proj_w, wp, C_DIM * C_DIM);

    // 1. GroupNorm -> h[b,s,c] fp16
    gn_stats_kernel<<<B_DIM * NG, 256>>>(x, meanA, invA);
    gn_transpose_kernel<<<dim3(32, 16, 16), dim3(32, 8)>>>(x, norm_w, norm_b,
                                                           meanA, invA, h);

    // 2. QKV: M=s(1024), N=o(1536), K=512. C[m*1536+n] fp16, bias per n.
    cudaFuncSetAttribute(hgemm_kernel<2, false, __half>,
                         cudaFuncAttributeMaxDynamicSharedMemorySize, HG_SMEM);
    hgemm_kernel<2, false, __half><<<dim3(6, 8, 16), 256, HG_SMEM>>>(
        h, wq, qkv, qkv_b, nullptr,
        512, 512, 512, 1536,
        1, SC, 0, 0, 0, S3C, 0, 1.0f);

    // 3. Fused flash attention -> obuf[b,s,c] fp16
    cudaFuncSetAttribute(flash_kernel,
                         cudaFuncAttributeMaxDynamicSharedMemorySize, FLASH_SMEM);
    flash_kernel<<<dim3(S_DIM / 128, B_DIM * NH), 256, FLASH_SMEM>>>(qkv, obuf);

    // 4. Proj: M=co(512), N=s(1024), K=512. C[m*1024+n] fp32, bias per m, resid=x.
    cudaFuncSetAttribute(hgemm_kernel<1, true, float>,
                         cudaFuncAttributeMaxDynamicSharedMemorySize, HG_SMEM);
    hgemm_kernel<1, true, float><<<dim3(4, 4, 16), 256, HG_SMEM>>>(
        wp, obuf, out, proj_b, x,
        512, 512, 512, 1024,
        1, 0, 0, SC, 0, SC, 0, 1.0f);
}

// round 7
// speedup vs baseline: 1.0627x; 1.0627x over previous
#include <cuda_runtime.h>
#include <cuda_fp16.h>
#include <cstdint>
#include <math.h>

#define B_DIM 16
#define C_DIM 512
#define S_DIM 1024
#define NG    32
#define NH    8
#define HD    64

// ---------------- scratch (allocation-free __device__ globals) ----------------
__device__ __half g_h   [(size_t)B_DIM * S_DIM * C_DIM];          // [b,s,c]  16 MB
__device__ __half g_qkv [(size_t)B_DIM * S_DIM * 3 * C_DIM];      // [b,s,o]  48 MB
__device__ __half g_o   [(size_t)B_DIM * S_DIM * C_DIM];          // [b,s,c]  16 MB
__device__ __half g_wq  [3 * C_DIM * C_DIM];
__device__ __half g_wp  [C_DIM * C_DIM];
__device__ float  g_mean[B_DIM * NG];
__device__ float  g_inv [B_DIM * NG];

// ---------------- helpers ----------------
__device__ __forceinline__ uint32_t smem_u32(const void* p) {
    return (uint32_t)__cvta_generic_to_shared(p);
}
__device__ __forceinline__ void cp16(void* smem_dst, const void* gmem_src) {
    asm volatile("cp.async.ca.shared.global [%0], [%1], 16;"
                 :: "r"(smem_u32(smem_dst)), "l"(gmem_src));
}
__device__ __forceinline__ void cp_commit() {
    asm volatile("cp.async.commit_group;" ::: "memory");
}
template <int N>
__device__ __forceinline__ void cp_wait() {
    asm volatile("cp.async.wait_group %0;" :: "n"(N) : "memory");
}
__device__ __forceinline__ void ldm_x4(uint32_t& r0, uint32_t& r1, uint32_t& r2,
                                       uint32_t& r3, const void* p) {
    asm volatile("ldmatrix.sync.aligned.m8n8.x4.shared.b16 {%0,%1,%2,%3}, [%4];"
                 : "=r"(r0), "=r"(r1), "=r"(r2), "=r"(r3) : "r"(smem_u32(p)));
}
__device__ __forceinline__ void ldm_x4t(uint32_t& r0, uint32_t& r1, uint32_t& r2,
                                        uint32_t& r3, const void* p) {
    asm volatile("ldmatrix.sync.aligned.m8n8.x4.trans.shared.b16 {%0,%1,%2,%3}, [%4];"
                 : "=r"(r0), "=r"(r1), "=r"(r2), "=r"(r3) : "r"(smem_u32(p)));
}
__device__ __forceinline__ void ldm_x2(uint32_t& r0, uint32_t& r1, const void* p) {
    asm volatile("ldmatrix.sync.aligned.m8n8.x2.shared.b16 {%0,%1}, [%2];"
                 : "=r"(r0), "=r"(r1) : "r"(smem_u32(p)));
}
__device__ __forceinline__ void mma16816(float* c, const uint32_t* a, const uint32_t* b) {
    asm volatile(
        "mma.sync.aligned.m16n8k16.row.col.f32.f16.f16.f32 "
        "{%0,%1,%2,%3}, {%4,%5,%6,%7}, {%8,%9}, {%0,%1,%2,%3};"
        : "+f"(c[0]), "+f"(c[1]), "+f"(c[2]), "+f"(c[3])
        : "r"(a[0]), "r"(a[1]), "r"(a[2]), "r"(a[3]), "r"(b[0]), "r"(b[1]));
}
__device__ __forceinline__ float ex2(float x) {
    float y;
    asm("ex2.approx.ftz.f32 %0, %1;" : "=f"(y) : "f"(x));
    return y;
}
__device__ __forceinline__ uint32_t ex2_h2(uint32_t x) {
    uint32_t y;
    asm("ex2.approx.f16x2 %0, %1;" : "=r"(y) : "r"(x));
    return y;
}
__device__ __forceinline__ uint32_t h2_as_u32(__half2 h) {
    return *reinterpret_cast<uint32_t*>(&h);
}
__device__ __forceinline__ __half2 u32_as_h2(uint32_t u) {
    return *reinterpret_cast<__half2*>(&u);
}

// ---------------------------------------------------------------------------
// fp32 -> fp16 weight convert (both weight matrices in one launch)
// ---------------------------------------------------------------------------
__global__ void convert_weights_kernel(const float* __restrict__ wq_f,
                                       const float* __restrict__ wp_f,
                                       __half* __restrict__ wq,
                                       __half* __restrict__ wp) {
    const int NQ = 3 * C_DIM * C_DIM;
    const int NP = C_DIM * C_DIM;
    int i = blockIdx.x * blockDim.x + threadIdx.x;
    if (i < NQ) wq[i] = __float2half(wq_f[i]);
    else if (i < NQ + NP) wp[i - NQ] = __float2half(wp_f[i - NQ]);
}

// ---------------------------------------------------------------------------
// GroupNorm pass 1: per (b,g) mean / inv-std
// ---------------------------------------------------------------------------
__global__ void gn_stats_kernel(const float* __restrict__ x,
                                float* __restrict__ meanArr,
                                float* __restrict__ invArr) {
    const int bg = blockIdx.x;
    const int NEL = (C_DIM / NG) * S_DIM;
    const float* xp = x + (size_t)bg * NEL;
    float sum = 0.f, sq = 0.f;
    for (int i = threadIdx.x; i < NEL; i += 256) {
        float v = xp[i];
        sum += v; sq += v * v;
    }
    __shared__ float ssum[256], ssq[256];
    ssum[threadIdx.x] = sum; ssq[threadIdx.x] = sq;
    __syncthreads();
    for (int s = 128; s > 0; s >>= 1) {
        if (threadIdx.x < s) {
            ssum[threadIdx.x] += ssum[threadIdx.x + s];
            ssq[threadIdx.x]  += ssq[threadIdx.x + s];
        }
        __syncthreads();
    }
    if (threadIdx.x == 0) {
        float mean = ssum[0] * (1.f / NEL);
        float var  = ssq[0] * (1.f / NEL) - mean * mean;
        meanArr[bg] = mean;
        invArr[bg]  = rsqrtf(var + 1e-5f);
    }
}

// ---------------------------------------------------------------------------
// GroupNorm pass 2 + transpose -> h[b,s,c] fp16.
// Tile: 64 channels x 32 spatial. Stores are half2 (128B/warp coalesced).
// ---------------------------------------------------------------------------
__global__ void gn_transpose_kernel(const float* __restrict__ x,
                                    const float* __restrict__ gamma,
                                    const float* __restrict__ beta,
                                    const float* __restrict__ meanArr,
                                    const float* __restrict__ invArr,
                                    __half* __restrict__ h) {
    __shared__ float t[64][33];
    const int b = blockIdx.z, c0 = blockIdx.y * 64, s0 = blockIdx.x * 32;
    const int tx = threadIdx.x, ty = threadIdx.y;
#pragma unroll
    for (int i = 0; i < 8; i++) {
        int cr = ty + i * 8;               // 0..63
        int c = c0 + cr;
        float v = x[((size_t)b * C_DIM + c) * S_DIM + s0 + tx];
        int g = c >> 4;
        float mean = meanArr[b * NG + g], inv = invArr[b * NG + g];
        t[cr][tx] = (v - mean) * inv * gamma[c] + beta[c];
    }
    __syncthreads();
#pragma unroll
    for (int i = 0; i < 4; i++) {
        int s = s0 + ty + i * 8;
        __half2 val = __floats2half2_rn(t[tx * 2][ty + i * 8],
                                        t[tx * 2 + 1][ty + i * 8]);
        *(__half2*)&h[((size_t)b * S_DIM + s) * C_DIM + c0 + tx * 2] = val;
    }
}

// ---------------------------------------------------------------------------
// Fused flash attention (fp16 mma, fp32 online softmax, f16x2 exp).
// Grid: (S/128, B*NH). 256 thr = 8 warps; warp w owns rows s0+w*16..+15.
// ---------------------------------------------------------------------------
#define SMK 72
#define FLASH_SMEM (5 * 128 * SMK * 2)

__global__ __launch_bounds__(256)
void flash_kernel(const __half* __restrict__ qkv, __half* __restrict__ o) {
    extern __shared__ __half sm[];
    __half (*Qs)[SMK] = reinterpret_cast<__half(*)[SMK]>(sm);
    __half (*Ks)[SMK] = reinterpret_cast<__half(*)[SMK]>(sm + 128 * SMK);
    __half (*Vs)[SMK] = reinterpret_cast<__half(*)[SMK]>(sm + 3 * 128 * SMK);

    const int tid = threadIdx.x, lane = tid & 31, w = tid >> 5;
    const int bh = blockIdx.y, b = bh >> 3, hh = bh & 7;
    const int s0 = blockIdx.x * 128;

    const __half* qbase = qkv + (size_t)b * (S_DIM * 3 * C_DIM) + hh * 64;
    const __half* kbase = qbase + 512;
    const __half* vbase = qbase + 1024;

    const int ldrow = tid >> 1;
    const int ldcol = (tid & 1) * 32;

#pragma unroll
    for (int c = 0; c < 4; c++)
        cp16(&Qs[ldrow][ldcol + c * 8],
             qbase + (size_t)(s0 + ldrow) * 1536 + ldcol + c * 8);
    cp_commit();
    {
        const __half* kp = kbase + (size_t)ldrow * 1536 + ldcol;
        const __half* vp = vbase + (size_t)ldrow * 1536 + ldcol;
#pragma unroll
        for (int c = 0; c < 4; c++) {
            cp16(&Ks[ldrow][ldcol + c * 8], kp + c * 8);
            cp16(&Vs[ldrow][ldcol + c * 8], vp + c * 8);
        }
    }
    cp_commit();
    cp_wait<1>();
    __syncthreads();

    uint32_t qf[4][4];
#pragma unroll
    for (int kj = 0; kj < 4; kj++)
        ldm_x4(qf[kj][0], qf[kj][1], qf[kj][2], qf[kj][3],
               &Qs[w * 16 + (lane & 15)][kj * 16 + ((lane >> 4) << 3)]);

    const float C2 = 0.125f * 1.44269504f;
    float m0 = -1e30f, m1 = -1e30f, l0 = 0.f, l1 = 0.f;
    float ao[8][4];
#pragma unroll
    for (int i = 0; i < 8; i++)
#pragma unroll
        for (int j = 0; j < 4; j++) ao[i][j] = 0.f;

    for (int it = 0; it < 8; it++) {
        if (it < 7) {
            const int stn = (it + 1) & 1;
            const __half* kp = kbase + (size_t)((it + 1) * 128 + ldrow) * 1536 + ldcol;
            const __half* vp = vbase + (size_t)((it + 1) * 128 + ldrow) * 1536 + ldcol;
#pragma unroll
            for (int c = 0; c < 4; c++) {
                cp16(&Ks[stn * 128 + ldrow][ldcol + c * 8], kp + c * 8);
                cp16(&Vs[stn * 128 + ldrow][ldcol + c * 8], vp + c * 8);
            }
            cp_commit();
            cp_wait<1>();
        } else {
            cp_wait<0>();
        }
        __syncthreads();
        const int st = it & 1;

        // ---- S = Q K^T ----
        float as[16][4];
#pragma unroll
        for (int i = 0; i < 16; i++)
#pragma unroll
            for (int j = 0; j < 4; j++) as[i][j] = 0.f;

#pragma unroll
        for (int kj = 0; kj < 4; kj++) {
            uint32_t bf[8][4];
#pragma unroll
            for (int j = 0; j < 8; j++)
                ldm_x4(bf[j][0], bf[j][1], bf[j][2], bf[j][3],
                       &Ks[st * 128 + j * 16 + (lane & 15)]
                          [kj * 16 + ((lane >> 4) << 3)]);
#pragma unroll
            for (int j = 0; j < 8; j++) {
                uint32_t bA[2] = {bf[j][0], bf[j][2]};
                uint32_t bB[2] = {bf[j][1], bf[j][3]};
                mma16816(as[2 * j],     qf[kj], bA);
                mma16816(as[2 * j + 1], qf[kj], bB);
            }
        }

        // ---- online softmax (f16x2 exp) ----
        float mx0 = -1e30f, mx1 = -1e30f;
#pragma unroll
        for (int nt = 0; nt < 16; nt++) {
            mx0 = fmaxf(mx0, fmaxf(as[nt][0], as[nt][1]));
            mx1 = fmaxf(mx1, fmaxf(as[nt][2], as[nt][3]));
        }
        mx0 = fmaxf(mx0, __shfl_xor_sync(0xffffffffu, mx0, 1));
        mx0 = fmaxf(mx0, __shfl_xor_sync(0xffffffffu, mx0, 2));
        mx1 = fmaxf(mx1, __shfl_xor_sync(0xffffffffu, mx1, 1));
        mx1 = fmaxf(mx1, __shfl_xor_sync(0xffffffffu, mx1, 2));
        const float mn0 = fmaxf(m0, mx0), mn1 = fmaxf(m1, mx1);
        const float cr0 = ex2((m0 - mn0) * C2), cr1 = ex2((m1 - mn1) * C2);
        m0 = mn0; m1 = mn1;
        l0 *= cr0; l1 *= cr1;
#pragma unroll
        for (int tn = 0; tn < 8; tn++) {
            ao[tn][0] *= cr0; ao[tn][1] *= cr0;
            ao[tn][2] *= cr1; ao[tn][3] *= cr1;
        }

        uint32_t ph[8][4];
        float sum0 = 0.f, sum1 = 0.f;
#pragma unroll
        for (int nt = 0; nt < 16; nt++) {
            uint32_t e01 = h2_as_u32(__floats2half2_rn((as[nt][0] - mn0) * C2,
                                                       (as[nt][1] - mn0) * C2));
            uint32_t e23 = h2_as_u32(__floats2half2_rn((as[nt][2] - mn1) * C2,
                                                       (as[nt][3] - mn1) * C2));
            uint32_t p01 = ex2_h2(e01);
            uint32_t p23 = ex2_h2(e23);
            float2 f01 = __half22float2(u32_as_h2(p01));
            float2 f23 = __half22float2(u32_as_h2(p23));
            sum0 += f01.x + f01.y;
            sum1 += f23.x + f23.y;
            const int kj = nt >> 1, hi = (nt & 1) * 2;
            ph[kj][hi]     = p01;
            ph[kj][hi + 1] = p23;
        }
        sum0 += __shfl_xor_sync(0xffffffffu, sum0, 1);
        sum0 += __shfl_xor_sync(0xffffffffu, sum0, 2);
        sum1 += __shfl_xor_sync(0xffffffffu, sum1, 1);
        sum1 += __shfl_xor_sync(0xffffffffu, sum1, 2);
        l0 += sum0; l1 += sum1;

        // ---- O += P V ----
#pragma unroll
        for (int kj = 0; kj < 8; kj++) {
            uint32_t vf[4][4];
#pragma unroll
            for (int dj = 0; dj < 4; dj++)
                ldm_x4t(vf[dj][0], vf[dj][1], vf[dj][2], vf[dj][3],
                        &Vs[st * 128 + kj * 16 + (lane & 15)]
                           [dj * 16 + ((lane >> 4) << 3)]);
#pragma unroll
            for (int dj = 0; dj < 4; dj++) {
                uint32_t bA[2] = {vf[dj][0], vf[dj][1]};
                uint32_t bB[2] = {vf[dj][2], vf[dj][3]};
                mma16816(ao[2 * dj],     ph[kj], bA);
                mma16816(ao[2 * dj + 1], ph[kj], bB);
            }
        }
        __syncthreads();
    }

    const float r0 = 1.f / l0, r1 = 1.f / l1;
    const int g = lane >> 2;
    const int srow = s0 + w * 16 + g;
    __half* op = o + ((size_t)b * S_DIM + srow) * C_DIM + hh * 64 + (lane & 3) * 2;
#pragma unroll
    for (int tn = 0; tn < 8; tn++) {
        *(__half2*)(op + tn * 8) =
            __floats2half2_rn(ao[tn][0] * r0, ao[tn][1] * r0);
        *(__half2*)(op + 8 * C_DIM + tn * 8) =
            __floats2half2_rn(ao[tn][2] * r1, ao[tn][3] * r1);
    }
}

// ---------------------------------------------------------------------------
// HGEMM via mma.sync m16n8k16 (fp16 in, fp32 acc) — R5 configuration.
// BM=128, BN=128, BK=32, 256 thr, 8 warps (2m x 4n), warp tile 64x32.
// ---------------------------------------------------------------------------
template <int BN, int BIAS_MODE, bool RESID, typename OutT>
__global__ __launch_bounds__(256)
void hgemm_kernel(const __half* __restrict__ A, const __half* __restrict__ B,
                  OutT* __restrict__ C, const float* __restrict__ bias,
                  const float* __restrict__ resid,
                  int K, int lda, int ldb, int ldc, int nInner,
                  long sAo, long sAi, long sBo, long sBi,
                  long sCo, long sCi, float alpha) {
    constexpr int BM = 128, BK = 32;
    constexpr int WN = BN / 4;
    constexpr int NT = WN / 8;
    constexpr int SK = BK + 8;

    __shared__ __half As[2][BM][SK];
    __shared__ __half Bs[2][BN][SK];

    const int tid = threadIdx.x;
    const int lane = tid & 31, wid = tid >> 5;
    const int wm = wid & 1, wn = wid >> 1;

    const int z = blockIdx.z;
    const int zo = z / nInner, zi = z - zo * nInner;
    A += zo * sAo + zi * sAi;
    B += zo * sBo + zi * sBi;
    const size_t cbase = (size_t)(zo * sCo + zi * sCi);
    const int m0 = blockIdx.y * BM;
    const int n0 = blockIdx.x * BN;

    const int lrow = tid >> 2;
    const int lcol = (tid & 3) * 8;

    float acc[4][NT][4];
#pragma unroll
    for (int i = 0; i < 4; i++)
#pragma unroll
        for (int j = 0; j < NT; j++)
#pragma unroll
            for (int q = 0; q < 4; q++) acc[i][j][q] = 0.f;

    const int nit = K >> 5;

    auto load_stage = [&](int st, int it) {
        const int k0 = it << 5;
#pragma unroll
        for (int p = 0; p < BM / 64; p++) {
            int r = lrow + p * 64;
            cp16(&As[st][r][lcol], A + (size_t)(m0 + r) * lda + k0 + lcol);
        }
#pragma unroll
        for (int p = 0; p < BN / 64; p++) {
            int r = lrow + p * 64;
            cp16(&Bs[st][r][lcol], B + (size_t)(n0 + r) * ldb + k0 + lcol);
        }
        cp_commit();
    };

    load_stage(0, 0);

    for (int it = 0; it < nit; it++) {
        if (it + 1 < nit) {
            load_stage((it + 1) & 1, it + 1);
            cp_wait<1>();
        } else {
            cp_wait<0>();
        }
        __syncthreads();

        const int st = it & 1;
#pragma unroll
        for (int ks = 0; ks < 2; ks++) {
            const int kb = ks * 16;
            uint32_t a[4][4], bfr[NT][2];
#pragma unroll
            for (int tm = 0; tm < 4; tm++)
                ldm_x4(a[tm][0], a[tm][1], a[tm][2], a[tm][3],
                       &As[st][wm * 64 + tm * 16 + (lane & 15)][kb + ((lane >> 4) << 3)]);
#pragma unroll
            for (int tn = 0; tn < NT; tn++)
                ldm_x2(bfr[tn][0], bfr[tn][1],
                       &Bs[st][wn * WN + tn * 8 + (lane & 7)][kb + ((lane >> 3) & 1) * 8]);
#pragma unroll
            for (int tm = 0; tm < 4; tm++)
#pragma unroll
                for (int tn = 0; tn < NT; tn++)
                    mma16816(acc[tm][tn], a[tm], bfr[tn]);
        }
        __syncthreads();
    }

#pragma unroll
    for (int tm = 0; tm < 4; tm++) {
        const int row = m0 + wm * 64 + tm * 16 + (lane >> 2);
#pragma unroll
        for (int tn = 0; tn < NT; tn++) {
            const int col = n0 + wn * WN + tn * 8 + (lane & 3) * 2;
            float v0 = acc[tm][tn][0] * alpha, v1 = acc[tm][tn][1] * alpha;
            float v2 = acc[tm][tn][2] * alpha, v3 = acc[tm][tn][3] * alpha;
            if (BIAS_MODE == 1) {
                v0 += bias[row]; v1 += bias[row];
                v2 += bias[row + 8]; v3 += bias[row + 8];
            }
            if (BIAS_MODE == 2) {
                v0 += bias[col]; v2 += bias[col];
                v1 += bias[col + 1]; v3 += bias[col + 1];
            }
            const size_t a0 = cbase + (size_t)row * ldc + col;
            const size_t a1 = cbase + (size_t)(row + 8) * ldc + col;
            if (sizeof(OutT) == 4) {
                float2 q0 = make_float2(v0, v1), q1 = make_float2(v2, v3);
                if (RESID) {
                    float2 x0 = *(const float2*)(resid + a0);
                    float2 x1 = *(const float2*)(resid + a1);
                    q0.x += x0.x; q0.y += x0.y; q1.x += x1.x; q1.y += x1.y;
                }
                *(float2*)((float*)C + a0) = q0;
                *(float2*)((float*)C + a1) = q1;
            } else {
                *(__half2*)((__half*)C + a0) = __floats2half2_rn(v0, v1);
                *(__half2*)((__half*)C + a1) = __floats2half2_rn(v2, v3);
            }
        }
    }
}

// ---------------------------------------------------------------------------
// Launch
// ---------------------------------------------------------------------------
extern "C" void kernel_launch(void* const* d_in, const int* in_sizes, int n_in,
                              void* d_out, int out_size) {
    const float* x      = (const float*)d_in[0];
    const float* norm_w = (const float*)d_in[1];
    const float* norm_b = (const float*)d_in[2];
    const float* qkv_w  = (const float*)d_in[3];
    const float* qkv_b  = (const float*)d_in[4];
    const float* proj_w = (const float*)d_in[5];
    const float* proj_b = (const float*)d_in[6];
    float* out = (float*)d_out;

    __half *h, *qkv, *obuf, *wq, *wp;
    float *meanA, *invA;
    cudaGetSymbolAddress((void**)&h,     g_h);
    cudaGetSymbolAddress((void**)&qkv,   g_qkv);
    cudaGetSymbolAddress((void**)&obuf,  g_o);
    cudaGetSymbolAddress((void**)&wq,    g_wq);
    cudaGetSymbolAddress((void**)&wp,    g_wp);
    cudaGetSymbolAddress((void**)&meanA, g_mean);
    cudaGetSymbolAddress((void**)&invA,  g_inv);

    const long SC  = (long)S_DIM * C_DIM;
    const long S3C = (long)S_DIM * 3 * C_DIM;

    // 0. fp16 weight copies (single launch)
    convert_weights_kernel<<<(4 * C_DIM * C_DIM + 255) / 256, 256>>>(
        qkv_w, proj_w, wq, wp);

    // 1. GroupNorm -> h[b,s,c] fp16
    gn_stats_kernel<<<B_DIM * NG, 256>>>(x, meanA, invA);
    gn_transpose_kernel<<<dim3(32, 8, 16), dim3(32, 8)>>>(x, norm_w, norm_b,
                                                          meanA, invA, h);

    // 2. QKV: M=s, N=o(1536), K=512. C[m*1536+n] = qkv[b,s,o] fp16, bias per n.
    hgemm_kernel<128, 2, false, __half><<<dim3(12, 8, 16), 256>>>(
        h, wq, qkv, qkv_b, nullptr,
        512, 512, 512, 1536,
        1, SC, 0, 0, 0, S3C, 0, 1.0f);

    // 3. Fused flash attention -> obuf[b,s,c] fp16
    cudaFuncSetAttribute(flash_kernel,
                         cudaFuncAttributeMaxDynamicSharedMemorySize, FLASH_SMEM);
    flash_kernel<<<dim3(S_DIM / 128, B_DIM * NH), 256, FLASH_SMEM>>>(qkv, obuf);

    // 4. Proj: M=co(512), N=s, K=512. C[m*1024+n] = out[b,co,s] fp32,
    //    bias per m, resid = x.
    hgemm_kernel<128, 1, true, float><<<dim3(8, 4, 16), 256>>>(
        wp, obuf, out, proj_b, x,
        512, 512, 512, 1024,
        1, 0, 0, SC, 0, SC, 0, 1.0f);
}